// round 9
// baseline (speedup 1.0000x reference)
#include <cuda_runtime.h>
#include <math.h>

#define NH 8
#define DHD 64
#define DMOD 512
#define SEQ 1024
#define NB 2
#define NBS (NB*SEQ)

// scratch (static device arrays: no allocation allowed)
__device__ float g_q[NB*NH*SEQ*DHD];
__device__ float g_k[NB*NH*SEQ*DHD];
__device__ float g_v[NB*NH*SEQ*DHD];
__device__ float g_attn[NBS*DMOD];
__device__ float g_y[NBS*DMOD];
__device__ float g_table[65*DHD];

// ---------------------------------------------------------------------------
// sincos relative-position table: pe[pos, 2j] = sin(pos*div_j), pe[pos,2j+1]=cos
__global__ void build_table_kernel() {
    int i = blockIdx.x * blockDim.x + threadIdx.x;
    if (i < 65*32) {
        int pos = i >> 5, j = i & 31;
        float div = expf((float)(2*j) * (-9.210340371976184f / 64.0f));
        float a = (float)pos * div;
        g_table[pos*64 + 2*j]     = sinf(a);
        g_table[pos*64 + 2*j + 1] = cosf(a);
    }
}

// ---------------------------------------------------------------------------
// Merged Q/K/V projection: z selects (A, W, bias, dst). C = A @ W^T + bias,
// scattered to [b,h,s,d]. 64x64 tile, k-step 32, 4x4 microtile. 768 CTAs.
__global__ __launch_bounds__(256) void gemm_qkv_kernel(
    const float* __restrict__ Aq, const float* __restrict__ Ak_, const float* __restrict__ Av,
    const float* __restrict__ Wq, const float* __restrict__ Wk, const float* __restrict__ Wv,
    const float* __restrict__ bq, const float* __restrict__ bk, const float* __restrict__ bv)
{
    __shared__ float As[64][36];   // [n][k]
    __shared__ float Ws[32][68];   // [k][m]
    int z = blockIdx.z;
    const float* A    = (z == 0) ? Aq : ((z == 1) ? Ak_ : Av);
    const float* W    = (z == 0) ? Wq : ((z == 1) ? Wk : Wv);
    const float* bias = (z == 0) ? bq : ((z == 1) ? bk : bv);
    float* dst        = (z == 0) ? g_q : ((z == 1) ? g_k : g_v);

    int tid = threadIdx.x;
    int tx = tid & 15, ty = tid >> 4;
    int n0 = blockIdx.y * 64;
    int m0 = blockIdx.x * 64;
    float acc[4][4] = {};
    for (int k0 = 0; k0 < DMOD; k0 += 32) {
#pragma unroll
        for (int j = 0; j < 2; j++) {
            int id = tid + 256*j;
            int row = id >> 3, c4 = (id & 7) * 4;
            *(float4*)&As[row][c4] = *(const float4*)(A + (size_t)(n0 + row)*DMOD + k0 + c4);
        }
#pragma unroll
        for (int j = 0; j < 2; j++) {
            int id = tid + 256*j;
            int row = id >> 3, c4 = (id & 7) * 4;
            float4 w4 = *(const float4*)(W + (size_t)(m0 + row)*DMOD + k0 + c4);
            Ws[c4+0][row] = w4.x; Ws[c4+1][row] = w4.y;
            Ws[c4+2][row] = w4.z; Ws[c4+3][row] = w4.w;
        }
        __syncthreads();
#pragma unroll
        for (int kk = 0; kk < 32; kk++) {
            float4 wf = *(const float4*)&Ws[kk][tx*4];
            float af[4];
#pragma unroll
            for (int r = 0; r < 4; r++) af[r] = As[ty*4+r][kk];
#pragma unroll
            for (int r = 0; r < 4; r++) {
                acc[r][0] += af[r]*wf.x; acc[r][1] += af[r]*wf.y;
                acc[r][2] += af[r]*wf.z; acc[r][3] += af[r]*wf.w;
            }
        }
        __syncthreads();
    }
#pragma unroll
    for (int r = 0; r < 4; r++) {
        int n = n0 + ty*4 + r;
        int b = n >> 10, s = n & 1023;
#pragma unroll
        for (int c = 0; c < 4; c++) {
            int m = m0 + tx*4 + c;
            int h = m >> 6, d = m & 63;
            dst[(((size_t)(b*NH + h) << 10) + s)*DHD + d] = acc[r][c] + bias[m];
        }
    }
}

// ---------------------------------------------------------------------------
// Output projection: y = attn @ Wo^T + bo + residual. 32x64 tiles, 512 CTAs,
// 2x4 microtile.
__global__ __launch_bounds__(256) void gemm_out_kernel(
    const float* __restrict__ W, const float* __restrict__ bias,
    const float* __restrict__ res)
{
    __shared__ float As[32][36];
    __shared__ float Ws[32][68];
    const float* A = g_attn;
    int tid = threadIdx.x;
    int tx = tid & 15, ty = tid >> 4;
    int n0 = blockIdx.y * 32;
    int m0 = blockIdx.x * 64;
    float acc[2][4] = {};
    for (int k0 = 0; k0 < DMOD; k0 += 32) {
        {
            int row = tid >> 3, c4 = (tid & 7) * 4;   // 32 rows x 8 float4
            *(float4*)&As[row][c4] = *(const float4*)(A + (size_t)(n0 + row)*DMOD + k0 + c4);
        }
#pragma unroll
        for (int j = 0; j < 2; j++) {
            int id = tid + 256*j;
            int row = id >> 3, c4 = (id & 7) * 4;     // 64 rows x 8 float4
            float4 w4 = *(const float4*)(W + (size_t)(m0 + row)*DMOD + k0 + c4);
            Ws[c4+0][row] = w4.x; Ws[c4+1][row] = w4.y;
            Ws[c4+2][row] = w4.z; Ws[c4+3][row] = w4.w;
        }
        __syncthreads();
#pragma unroll
        for (int kk = 0; kk < 32; kk++) {
            float4 wf = *(const float4*)&Ws[kk][tx*4];
            float a0 = As[ty*2+0][kk];
            float a1 = As[ty*2+1][kk];
            acc[0][0] += a0*wf.x; acc[0][1] += a0*wf.y;
            acc[0][2] += a0*wf.z; acc[0][3] += a0*wf.w;
            acc[1][0] += a1*wf.x; acc[1][1] += a1*wf.y;
            acc[1][2] += a1*wf.z; acc[1][3] += a1*wf.w;
        }
        __syncthreads();
    }
#pragma unroll
    for (int r = 0; r < 2; r++) {
        int n = n0 + ty*2 + r;
        int m = m0 + tx*4;
        const float4 rv = *(const float4*)(res + (size_t)n*DMOD + m);
        float4 ov;
        ov.x = acc[r][0] + bias[m+0] + rv.x;
        ov.y = acc[r][1] + bias[m+1] + rv.y;
        ov.z = acc[r][2] + bias[m+2] + rv.z;
        ov.w = acc[r][3] + bias[m+3] + rv.w;
        *(float4*)(g_y + (size_t)n*DMOD + m) = ov;
    }
}

// ---------------------------------------------------------------------------
// Fused causal flash attention with relative-position bias (scores & values).
// BQ=32, BK=64. Grid: 512 blocks (32 q-tiles x 16 bh), heavy q-tiles first.
// 256 threads, 2x4 microtile. Static smem 47.0 KB -> ~4 CTAs/SM, one wave.
__global__ __launch_bounds__(256) void attn_kernel() {
    __shared__ float Qs[32][68];    // [q][d]
    __shared__ float KP[64][68];    // phase A: K^T [d][k]; phase B: P [q][k] (rows 0..31)
    __shared__ float Vs[64][68];    // [k][d]
    __shared__ float rel[32][34];   // [q][j], j=0..32
    __shared__ float mrow[32], lrowv[32];

    int tid = threadIdx.x;
    int tx = tid & 15, ty = tid >> 4;     // tx: 4 cols, ty: 2 rows
    int bid = blockIdx.x;
    int qb = 31 - (bid >> 4);             // heavy tiles first
    int bh = bid & 15;
    const float* qptr = g_q + ((size_t)bh*SEQ + qb*32)*DHD;

    // load Q tile: 32 rows x 16 float4 = 512 float4 / 256 threads = 2 each
#pragma unroll
    for (int i = 0; i < 2; i++) {
        int idx = tid + 256*i;
        int row = idx >> 4, c4 = (idx & 15) * 4;
        *(float4*)&Qs[row][c4] = *(const float4*)(qptr + row*DHD + c4);
    }
    __syncthreads();
    // rel[row][j] = q_row . table[j], j in [0,32]: 32*33 = 1056 dots
    for (int pidx = tid; pidx < 32*33; pidx += 256) {
        int row = pidx / 33;
        int j = pidx - row*33;
        const float* t = g_table + j*DHD;
        float s = 0.f;
#pragma unroll
        for (int d = 0; d < 64; d += 4) {
            float4 tv = *(const float4*)(t + d);
            s += Qs[row][d]*tv.x + Qs[row][d+1]*tv.y
               + Qs[row][d+2]*tv.z + Qs[row][d+3]*tv.w;
        }
        rel[row][j] = s;
    }

    float m_i[2], l_i[2], o[2][4];
#pragma unroll
    for (int r = 0; r < 2; r++) {
        m_i[r] = -1e30f; l_i[r] = 0.f;
#pragma unroll
        for (int c = 0; c < 4; c++) o[r][c] = 0.f;
    }

    int ntile = (qb >> 1) + 1;    // 64-wide key tiles covering kg <= qb*32+31
    for (int kb = 0; kb < ntile; kb++) {
        __syncthreads();          // KP/Vs free for reload (covers rel writes on iter 0)
        const float* kptr = g_k + ((size_t)bh*SEQ + kb*64)*DHD;
        const float* vptr = g_v + ((size_t)bh*SEQ + kb*64)*DHD;
#pragma unroll
        for (int i = 0; i < 4; i++) {
            int idx = tid + 256*i;            // 1024 = 64 rows * 16 float4
            int row = idx >> 4, c4 = (idx & 15) * 4;
            float4 kv = *(const float4*)(kptr + row*DHD + c4);
            KP[c4+0][row] = kv.x; KP[c4+1][row] = kv.y;
            KP[c4+2][row] = kv.z; KP[c4+3][row] = kv.w;
            *(float4*)&Vs[row][c4] = *(const float4*)(vptr + row*DHD + c4);
        }
        __syncthreads();

        // S = Q @ K^T  (32 x 64 tile; each thread: 2 rows x 4 cols)
        float s4[2][4] = {};
#pragma unroll
        for (int kk = 0; kk < 64; kk++) {
            float4 kf = *(const float4*)&KP[kk][tx*4];
            float q0 = Qs[ty*2+0][kk];
            float q1 = Qs[ty*2+1][kk];
            s4[0][0] += q0*kf.x; s4[0][1] += q0*kf.y;
            s4[0][2] += q0*kf.z; s4[0][3] += q0*kf.w;
            s4[1][0] += q1*kf.x; s4[1][1] += q1*kf.y;
            s4[1][2] += q1*kf.z; s4[1][3] += q1*kf.w;
        }

        float p4[2][4];
#pragma unroll
        for (int rr = 0; rr < 2; rr++) {
            int qg = qb*32 + ty*2 + rr;
#pragma unroll
            for (int c = 0; c < 4; c++) {
                int kg = kb*64 + tx*4 + c;
                if (kg > qg) s4[rr][c] = -1e30f;
                else {
                    int j = kg - qg + 32; if (j < 0) j = 0;
                    s4[rr][c] = (s4[rr][c] + rel[ty*2+rr][j]) * 0.125f;
                }
            }
            float mt = fmaxf(fmaxf(s4[rr][0], s4[rr][1]), fmaxf(s4[rr][2], s4[rr][3]));
#pragma unroll
            for (int off = 8; off >= 1; off >>= 1)
                mt = fmaxf(mt, __shfl_xor_sync(0xffffffffu, mt, off));
            float mn = fmaxf(m_i[rr], mt);
            float sc = __expf(m_i[rr] - mn);
            float rs = 0.f;
#pragma unroll
            for (int c = 0; c < 4; c++) {
                float p = __expf(s4[rr][c] - mn);
                p4[rr][c] = p; rs += p;
            }
#pragma unroll
            for (int off = 8; off >= 1; off >>= 1)
                rs += __shfl_xor_sync(0xffffffffu, rs, off);
            l_i[rr] = l_i[rr]*sc + rs;
            m_i[rr] = mn;
#pragma unroll
            for (int c = 0; c < 4; c++) o[rr][c] *= sc;
        }
        __syncthreads();      // all K reads done before P overwrites KP rows 0..31
#pragma unroll
        for (int rr = 0; rr < 2; rr++)
            *(float4*)&KP[ty*2+rr][tx*4] =
                make_float4(p4[rr][0], p4[rr][1], p4[rr][2], p4[rr][3]);
        __syncthreads();

        // O += P @ V  (32 x 64; each thread: 2 rows x 4 cols over d)
#pragma unroll
        for (int kk = 0; kk < 64; kk++) {
            float4 vf = *(const float4*)&Vs[kk][tx*4];
            float pv0 = KP[ty*2+0][kk];
            float pv1 = KP[ty*2+1][kk];
            o[0][0] += pv0*vf.x; o[0][1] += pv0*vf.y;
            o[0][2] += pv0*vf.z; o[0][3] += pv0*vf.w;
            o[1][0] += pv1*vf.x; o[1][1] += pv1*vf.y;
            o[1][2] += pv1*vf.z; o[1][3] += pv1*vf.w;
        }
    }

    // finalize p@v part
#pragma unroll
    for (int rr = 0; rr < 2; rr++) {
        float inv = 1.0f / l_i[rr];
#pragma unroll
        for (int c = 0; c < 4; c++) o[rr][c] *= inv;
    }
    if (tx == 0) {
#pragma unroll
        for (int rr = 0; rr < 2; rr++) { mrow[ty*2+rr] = m_i[rr]; lrowv[ty*2+rr] = l_i[rr]; }
    }
    __syncthreads();

    // rel-V band: p(q, q-mm), mm = 0..31 (recompute; bucket identity:
    // out2 = table[0] + sum_mm p * (table[32-mm] - table[0]) since sum_k p = 1)
    // bandp reuses KP rows 0..31 (P dead), stride 68.
#pragma unroll
    for (int i = 0; i < 4; i++) {
        int pidx = tid + 256*i;          // 1024 = 32 rows * 32 band offsets
        int row = pidx >> 5, mm = pidx & 31;
        int qg = qb*32 + row;
        int kg = qg - mm;
        float p = 0.f;
        if (kg >= 0) {
            const float* kvec = g_k + ((size_t)bh*SEQ + kg)*DHD;
            float dot = 0.f;
#pragma unroll
            for (int d = 0; d < 64; d += 4) {
                float4 kv = *(const float4*)(kvec + d);
                dot += Qs[row][d]*kv.x + Qs[row][d+1]*kv.y
                     + Qs[row][d+2]*kv.z + Qs[row][d+3]*kv.w;
            }
            float s = (dot + rel[row][32 - mm]) * 0.125f;
            p = __expf(s - mrow[row]) / lrowv[row];
        }
        KP[row][mm] = p;
    }
    __syncthreads();

    float4 t0v = *(const float4*)&g_table[tx*4];
    float4 a2[2];
#pragma unroll
    for (int rr = 0; rr < 2; rr++) a2[rr] = t0v;
    for (int mm = 0; mm < 32; mm++) {
        float4 tv = *(const float4*)&g_table[(32 - mm)*64 + tx*4];
        float4 dv = make_float4(tv.x - t0v.x, tv.y - t0v.y, tv.z - t0v.z, tv.w - t0v.w);
#pragma unroll
        for (int rr = 0; rr < 2; rr++) {
            float pm = KP[ty*2+rr][mm];
            a2[rr].x += pm*dv.x; a2[rr].y += pm*dv.y;
            a2[rr].z += pm*dv.z; a2[rr].w += pm*dv.w;
        }
    }
    int b = bh >> 3, h = bh & 7;
#pragma unroll
    for (int rr = 0; rr < 2; rr++) {
        int sg = qb*32 + ty*2 + rr;
        float4 ov = make_float4(o[rr][0] + a2[rr].x, o[rr][1] + a2[rr].y,
                                o[rr][2] + a2[rr].z, o[rr][3] + a2[rr].w);
        *(float4*)&g_attn[((size_t)b*SEQ + sg)*DMOD + h*64 + tx*4] = ov;
    }
}

// ---------------------------------------------------------------------------
// LayerNorm variant: unbiased std (ddof=1), divide by (std + eps)
__global__ __launch_bounds__(128) void ln_kernel(const float* __restrict__ lnw,
                                                 const float* __restrict__ lnb,
                                                 float* __restrict__ out)
{
    int rowid = blockIdx.x;
    const float* x = g_y + (size_t)rowid * DMOD;
    int tid = threadIdx.x;
    float4 xv = *(const float4*)(x + tid*4);
    float s  = xv.x + xv.y + xv.z + xv.w;
    float ss = xv.x*xv.x + xv.y*xv.y + xv.z*xv.z + xv.w*xv.w;
#pragma unroll
    for (int off = 16; off >= 1; off >>= 1) {
        s  += __shfl_xor_sync(0xffffffffu, s, off);
        ss += __shfl_xor_sync(0xffffffffu, ss, off);
    }
    __shared__ float rs[4], rss[4];
    int warp = tid >> 5;
    if ((tid & 31) == 0) { rs[warp] = s; rss[warp] = ss; }
    __syncthreads();
    float tS  = rs[0] + rs[1] + rs[2] + rs[3];
    float tSS = rss[0] + rss[1] + rss[2] + rss[3];
    float mean = tS * (1.0f/512.0f);
    float var = (tSS - 512.0f*mean*mean) * (1.0f/511.0f);
    var = fmaxf(var, 0.f);
    float inv = 1.0f / (sqrtf(var) + 1e-6f);
    float4 wv = *(const float4*)(lnw + tid*4);
    float4 bv = *(const float4*)(lnb + tid*4);
    float4 ov;
    ov.x = wv.x * (xv.x - mean) * inv + bv.x;
    ov.y = wv.y * (xv.y - mean) * inv + bv.y;
    ov.z = wv.z * (xv.z - mean) * inv + bv.z;
    ov.w = wv.w * (xv.w - mean) * inv + bv.w;
    *(float4*)(out + (size_t)rowid*DMOD + tid*4) = ov;
}

// ---------------------------------------------------------------------------
extern "C" void kernel_launch(void* const* d_in, const int* in_sizes, int n_in,
                              void* d_out, int out_size)
{
    const float* query = (const float*)d_in[0];
    const float* key_  = (const float*)d_in[1];
    const float* value = (const float*)d_in[2];
    const float* Wq = (const float*)d_in[3];
    const float* bq = (const float*)d_in[4];
    const float* Wk = (const float*)d_in[5];
    const float* bk = (const float*)d_in[6];
    const float* Wv = (const float*)d_in[7];
    const float* bv = (const float*)d_in[8];
    const float* Wo = (const float*)d_in[9];
    const float* bo = (const float*)d_in[10];
    const float* lnw = (const float*)d_in[11];
    const float* lnb = (const float*)d_in[12];
    float* out = (float*)d_out;
    (void)in_sizes; (void)n_in; (void)out_size;

    build_table_kernel<<<3, 1024>>>();
    gemm_qkv_kernel<<<dim3(8, 32, 3), 256>>>(query, key_, value,
                                             Wq, Wk, Wv, bq, bk, bv);
    attn_kernel<<<512, 256>>>();
    gemm_out_kernel<<<dim3(8, 64), 256>>>(Wo, bo, query);
    ln_kernel<<<NBS, 128>>>(lnw, lnb, out);
}